// round 1
// baseline (speedup 1.0000x reference)
#include <cuda_runtime.h>

#define N_NODES 100000
#define D_IN    512
#define D_HID   256
#define D_OUT   32

// Scratch (device globals: no runtime allocation allowed)
__device__ float g_h[(size_t)N_NODES * D_HID];   // 102.4 MB
__device__ float g_x[(size_t)N_NODES * D_OUT];   // 12.8 MB

// ---------------------------------------------------------------------------
// GEMM1: h = relu(F @ W1 + b1)    F[100000,512] * W1[512,256]
// Tile: BM=128, BN=128, BK=16, 256 threads, 8x8 register tile per thread.
// ---------------------------------------------------------------------------
#define BM 128
#define BN 128
#define BK 16
#define TM 8
#define TN 8
#define AS_LD 132   // padded stride for transposed A tile (keeps 16B alignment)

__global__ __launch_bounds__(256) void gemm1_relu_kernel(
    const float* __restrict__ F,
    const float* __restrict__ W1,
    const float* __restrict__ b1)
{
    __shared__ float As[BK * AS_LD];  // As[k*AS_LD + m]  (transposed)
    __shared__ float Bs[BK * BN];     // Bs[k*BN + n]

    const int t  = threadIdx.x;
    const int tx = t & 15;   // N direction
    const int ty = t >> 4;   // M direction
    const int m0 = blockIdx.x * BM;
    const int n0 = blockIdx.y * BN;

    float acc[TM][TN];
#pragma unroll
    for (int i = 0; i < TM; i++)
#pragma unroll
        for (int j = 0; j < TN; j++) acc[i][j] = 0.f;

    for (int k0 = 0; k0 < D_IN; k0 += BK) {
        // Load A tile: 128 rows x 16 cols = 512 float4 (2 per thread),
        // store transposed into As.
#pragma unroll
        for (int i = 0; i < 2; i++) {
            int L   = t + 256 * i;
            int row = L >> 2;        // 0..127
            int c4  = L & 3;         // 0..3
            int gm  = m0 + row;
            float4 v = make_float4(0.f, 0.f, 0.f, 0.f);
            if (gm < N_NODES)
                v = *(const float4*)(F + (size_t)gm * D_IN + k0 + c4 * 4);
            As[(c4 * 4 + 0) * AS_LD + row] = v.x;
            As[(c4 * 4 + 1) * AS_LD + row] = v.y;
            As[(c4 * 4 + 2) * AS_LD + row] = v.z;
            As[(c4 * 4 + 3) * AS_LD + row] = v.w;
        }
        // Load B tile: 16 rows x 128 cols = 512 float4 (2 per thread).
#pragma unroll
        for (int i = 0; i < 2; i++) {
            int L  = t + 256 * i;
            int kr = L >> 5;         // 0..15
            int c4 = L & 31;         // 0..31
            float4 v = *(const float4*)(W1 + (size_t)(k0 + kr) * D_HID + n0 + c4 * 4);
            *(float4*)(Bs + kr * BN + c4 * 4) = v;
        }
        __syncthreads();

#pragma unroll
        for (int k = 0; k < BK; k++) {
            float4 a0 = *(const float4*)(As + k * AS_LD + ty * TM);
            float4 a1 = *(const float4*)(As + k * AS_LD + ty * TM + 4);
            float4 b0 = *(const float4*)(Bs + k * BN + tx * TN);
            float4 b1v = *(const float4*)(Bs + k * BN + tx * TN + 4);
            float a[TM] = {a0.x, a0.y, a0.z, a0.w, a1.x, a1.y, a1.z, a1.w};
            float b[TN] = {b0.x, b0.y, b0.z, b0.w, b1v.x, b1v.y, b1v.z, b1v.w};
#pragma unroll
            for (int i = 0; i < TM; i++)
#pragma unroll
                for (int j = 0; j < TN; j++)
                    acc[i][j] = fmaf(a[i], b[j], acc[i][j]);
        }
        __syncthreads();
    }

    // Epilogue: + b1, relu, store to g_h
    float bias[TN];
#pragma unroll
    for (int j = 0; j < TN; j++) bias[j] = __ldg(b1 + n0 + tx * TN + j);

#pragma unroll
    for (int i = 0; i < TM; i++) {
        int gm = m0 + ty * TM + i;
        if (gm >= N_NODES) continue;
        float* hrow = g_h + (size_t)gm * D_HID + n0 + tx * TN;
#pragma unroll
        for (int j = 0; j < TN; j += 4) {
            float4 r;
            r.x = fmaxf(acc[i][j + 0] + bias[j + 0], 0.f);
            r.y = fmaxf(acc[i][j + 1] + bias[j + 1], 0.f);
            r.z = fmaxf(acc[i][j + 2] + bias[j + 2], 0.f);
            r.w = fmaxf(acc[i][j + 3] + bias[j + 3], 0.f);
            *(float4*)(hrow + j) = r;
        }
    }
}

// ---------------------------------------------------------------------------
// GEMM2: X = h @ W2 + b2      h[100000,256] * W2[256,32]
// One warp per output row; lane = output column; W2 resident in smem.
// ---------------------------------------------------------------------------
__global__ __launch_bounds__(256) void gemm2_kernel(
    const float* __restrict__ W2,
    const float* __restrict__ b2)
{
    __shared__ float Ws[D_HID * D_OUT];  // 32 KB
    const int t = threadIdx.x;
    for (int i = t; i < D_HID * D_OUT; i += 256)
        Ws[i] = W2[i];
    __syncthreads();

    const int warp = t >> 5;
    const int lane = t & 31;
    const int row  = blockIdx.x * 8 + warp;
    if (row >= N_NODES) return;

    const float4* h4 = (const float4*)(g_h + (size_t)row * D_HID);
    float acc = __ldg(b2 + lane);
#pragma unroll
    for (int kk = 0; kk < D_HID / 4; kk++) {
        float4 hv = h4[kk];   // broadcast across the warp
        acc = fmaf(hv.x, Ws[(4 * kk + 0) * 32 + lane], acc);
        acc = fmaf(hv.y, Ws[(4 * kk + 1) * 32 + lane], acc);
        acc = fmaf(hv.z, Ws[(4 * kk + 2) * 32 + lane], acc);
        acc = fmaf(hv.w, Ws[(4 * kk + 3) * 32 + lane], acc);
    }
    g_x[(size_t)row * D_OUT + lane] = acc;
}

// ---------------------------------------------------------------------------
// Zero output (d_out is poisoned by the harness)
// ---------------------------------------------------------------------------
__global__ void zero_kernel(float4* out, int n4)
{
    int i = blockIdx.x * blockDim.x + threadIdx.x;
    if (i < n4) out[i] = make_float4(0.f, 0.f, 0.f, 0.f);
}

// ---------------------------------------------------------------------------
// Scatter: out[A_row[e], :] += A_data[e] * X[A_col[e], :]
// 8 threads per edge, 4 dims (one float4 gather) per thread.
// ---------------------------------------------------------------------------
__global__ __launch_bounds__(256) void scatter_kernel(
    const float* __restrict__ A_data,
    const int*   __restrict__ A_row,
    const int*   __restrict__ A_col,
    float*       __restrict__ out,
    int n_edges)
{
    int idx = blockIdx.x * blockDim.x + threadIdx.x;
    int e = idx >> 3;
    int q = idx & 7;
    if (e >= n_edges) return;

    float a = __ldg(A_data + e);
    int   r = __ldg(A_row + e);
    int   c = __ldg(A_col + e);

    float4 xv = *(const float4*)(g_x + (size_t)c * D_OUT + q * 4);
    float* o  = out + (size_t)r * D_OUT + q * 4;
    atomicAdd(o + 0, a * xv.x);
    atomicAdd(o + 1, a * xv.y);
    atomicAdd(o + 2, a * xv.z);
    atomicAdd(o + 3, a * xv.w);
}

// ---------------------------------------------------------------------------
extern "C" void kernel_launch(void* const* d_in, const int* in_sizes, int n_in,
                              void* d_out, int out_size)
{
    const float* F      = (const float*)d_in[0];
    const float* A_data = (const float*)d_in[1];
    const float* W1     = (const float*)d_in[2];
    const float* b1     = (const float*)d_in[3];
    const float* W2     = (const float*)d_in[4];
    const float* b2     = (const float*)d_in[5];
    const int*   A_row  = (const int*)d_in[6];
    const int*   A_col  = (const int*)d_in[7];
    float* out = (float*)d_out;

    const int n_edges = in_sizes[1];

    // GEMM1 + relu
    dim3 g1((N_NODES + BM - 1) / BM, D_HID / BN);
    gemm1_relu_kernel<<<g1, 256>>>(F, W1, b1);

    // GEMM2
    gemm2_kernel<<<(N_NODES + 7) / 8, 256>>>(W2, b2);

    // Zero output
    int n4 = out_size / 4;
    zero_kernel<<<(n4 + 255) / 256, 256>>>((float4*)out, n4);

    // Scatter
    long long tot = (long long)n_edges * 8;
    int blocks = (int)((tot + 255) / 256);
    scatter_kernel<<<blocks, 256>>>(A_data, A_row, A_col, out, n_edges);
}

// round 3
// speedup vs baseline: 1.4956x; 1.4956x over previous
#include <cuda_runtime.h>
#include <cstdint>

#define N_NODES 100000
#define D_IN    512
#define D_HID   256
#define D_OUT   32

// Scratch (device globals: no runtime allocation allowed)
__device__ float g_h[(size_t)N_NODES * D_HID];   // 102.4 MB
__device__ float g_x[(size_t)N_NODES * D_OUT];   // 12.8 MB
__device__ float g_w1t[D_HID * D_IN];            // W1^T, tf32-rounded

// ---------------------------------------------------------------------------
__device__ __forceinline__ float tf32_rna(float x) {
    uint32_t u;
    asm("cvt.rna.tf32.f32 %0, %1;" : "=r"(u) : "f"(x));
    return __uint_as_float(u);
}

__device__ __forceinline__ void mma_tf32(
    float& d0, float& d1, float& d2, float& d3,
    float a0, float a1, float a2, float a3,
    float b0, float b1)
{
    asm volatile(
        "mma.sync.aligned.m16n8k8.row.col.f32.tf32.tf32.f32 "
        "{%0,%1,%2,%3},{%4,%5,%6,%7},{%8,%9},{%0,%1,%2,%3};"
        : "+f"(d0), "+f"(d1), "+f"(d2), "+f"(d3)
        : "r"(__float_as_uint(a0)), "r"(__float_as_uint(a1)),
          "r"(__float_as_uint(a2)), "r"(__float_as_uint(a3)),
          "r"(__float_as_uint(b0)), "r"(__float_as_uint(b1)));
}

// ---------------------------------------------------------------------------
// Prep: W1[k][n] -> g_w1t[n][k], tf32-rounded. grid(16,8), block(32,8)
// ---------------------------------------------------------------------------
__global__ void prep_w1_kernel(const float* __restrict__ W1) {
    __shared__ float tile[32][33];
    const int tx = threadIdx.x;
    const int ty = threadIdx.y;
    const int kb = blockIdx.x * 32;
    const int nb = blockIdx.y * 32;
#pragma unroll
    for (int i = 0; i < 4; i++) {
        int k = ty + i * 8;
        tile[k][tx] = W1[(size_t)(kb + k) * D_HID + nb + tx];
    }
    __syncthreads();
#pragma unroll
    for (int i = 0; i < 4; i++) {
        int n = ty + i * 8;
        g_w1t[(size_t)(nb + n) * D_IN + kb + tx] = tf32_rna(tile[tx][n]);
    }
}

// ---------------------------------------------------------------------------
// GEMM1: h = relu(F @ W1 + b1), mma.sync tf32.
// CTA 128x128x32, 8 warps (2 M x 4 N), warp tile 64x32.
// SMEM k-permuted layout: element at k-col c lives at pos (c&3)*8 + (c>>2),
// row stride 36 floats -> all fragment loads are contiguous LDS.128,
// bank-conflict-free.
// ---------------------------------------------------------------------------
#define G1_BK   32
#define G1_KIT  (D_IN / G1_BK)     // 16
#define G1_LD   36                 // padded floats per smem row
#define G1_BUF  (128 * G1_LD)      // floats per A (or B) tile
#define G1_SMEM (2 * 2 * G1_BUF * 4)  // 73728 bytes

__global__ __launch_bounds__(256) void gemm1_mma_kernel(
    const float* __restrict__ F,
    const float* __restrict__ b1)
{
    extern __shared__ float sm[];
    const int t    = threadIdx.x;
    const int lane = t & 31;
    const int wid  = t >> 5;
    const int wm   = wid & 1;       // warp M index (0..1)
    const int wn   = wid >> 1;      // warp N index (0..3)
    const int g    = lane >> 2;     // group id (0..7)
    const int tig  = lane & 3;      // thread in group

    const int m0 = blockIdx.x * 128;
    const int n0 = blockIdx.y * 128;

    // Staging assignment: thread covers row (t>>1), k-halves via (t&1)
    const int srow = t >> 1;            // 0..127
    const int kq   = (t & 1) * 16;      // k offset within BK tile
    const int spos = (t & 1) * 4;       // smem sub-position base (cb>>2)

    int arow = m0 + srow;
    if (arow >= N_NODES) arow = N_NODES - 1;   // clamp; epilogue guards store
    const float* Ag = F + (size_t)arow * D_IN + kq;
    const float* Bg = g_w1t + (size_t)(n0 + srow) * D_IN + kq;

    float4 ra[4], rb[4];

    // ---- load k-block 0 ----
#pragma unroll
    for (int q = 0; q < 4; q++) {
        ra[q] = *(const float4*)(Ag + q * 4);
        rb[q] = *(const float4*)(Bg + q * 4);
    }

    // ---- store to smem buffer 0 ----
    {
        float* As = sm;
        float* Bs = sm + G1_BUF;
#pragma unroll
        for (int q = 0; q < 4; q++) {
            int p = srow * G1_LD + spos + q;
            As[p + 0 ]  = tf32_rna(ra[q].x);
            As[p + 8 ]  = tf32_rna(ra[q].y);
            As[p + 16]  = tf32_rna(ra[q].z);
            As[p + 24]  = tf32_rna(ra[q].w);
            Bs[p + 0 ]  = rb[q].x;
            Bs[p + 8 ]  = rb[q].y;
            Bs[p + 16]  = rb[q].z;
            Bs[p + 24]  = rb[q].w;
        }
    }
    __syncthreads();

    float acc[4][4][4];
#pragma unroll
    for (int i = 0; i < 4; i++)
#pragma unroll
        for (int j = 0; j < 4; j++)
#pragma unroll
            for (int c = 0; c < 4; c++) acc[i][j][c] = 0.f;

    const int am = wm * 64;   // warp M base within tile
    const int bn = wn * 32;   // warp N base within tile

    for (int kb = 0; kb < G1_KIT; kb++) {
        // prefetch next k-block into registers
        if (kb + 1 < G1_KIT) {
            const float* pa = Ag + (kb + 1) * G1_BK;
            const float* pb = Bg + (kb + 1) * G1_BK;
#pragma unroll
            for (int q = 0; q < 4; q++) {
                ra[q] = *(const float4*)(pa + q * 4);
                rb[q] = *(const float4*)(pb + q * 4);
            }
        }

        const float* As = sm + (kb & 1) * 2 * G1_BUF;
        const float* Bs = As + G1_BUF;

#pragma unroll
        for (int j = 0; j < 2; j++) {
            // fragment loads: contiguous float4 thanks to the k-permutation
            float4 afl[4], afh[4], bf[4];
#pragma unroll
            for (int mt = 0; mt < 4; mt++) {
                int r = am + mt * 16 + g;
                afl[mt] = *(const float4*)(As + r * G1_LD + tig * 8 + j * 4);
                afh[mt] = *(const float4*)(As + (r + 8) * G1_LD + tig * 8 + j * 4);
            }
#pragma unroll
            for (int nt = 0; nt < 4; nt++) {
                int n = bn + nt * 8 + g;
                bf[nt] = *(const float4*)(Bs + n * G1_LD + tig * 8 + j * 4);
            }
            // two k-steps per float4
#pragma unroll
            for (int mt = 0; mt < 4; mt++) {
#pragma unroll
                for (int nt = 0; nt < 4; nt++) {
                    mma_tf32(acc[mt][nt][0], acc[mt][nt][1],
                             acc[mt][nt][2], acc[mt][nt][3],
                             afl[mt].x, afh[mt].x, afl[mt].y, afh[mt].y,
                             bf[nt].x,  bf[nt].y);
                    mma_tf32(acc[mt][nt][0], acc[mt][nt][1],
                             acc[mt][nt][2], acc[mt][nt][3],
                             afl[mt].z, afh[mt].z, afl[mt].w, afh[mt].w,
                             bf[nt].z,  bf[nt].w);
                }
            }
        }

        // stage next k-block into the other buffer
        if (kb + 1 < G1_KIT) {
            float* Aw = sm + ((kb + 1) & 1) * 2 * G1_BUF;
            float* Bw = Aw + G1_BUF;
#pragma unroll
            for (int q = 0; q < 4; q++) {
                int p = srow * G1_LD + spos + q;
                Aw[p + 0 ] = tf32_rna(ra[q].x);
                Aw[p + 8 ] = tf32_rna(ra[q].y);
                Aw[p + 16] = tf32_rna(ra[q].z);
                Aw[p + 24] = tf32_rna(ra[q].w);
                Bw[p + 0 ] = rb[q].x;
                Bw[p + 8 ] = rb[q].y;
                Bw[p + 16] = rb[q].z;
                Bw[p + 24] = rb[q].w;
            }
            __syncthreads();
        }
    }

    // ---- epilogue: bias + relu + store float2 pairs ----
#pragma unroll
    for (int mt = 0; mt < 4; mt++) {
        const int r0 = m0 + am + mt * 16 + g;
#pragma unroll
        for (int nt = 0; nt < 4; nt++) {
            const int col = n0 + bn + nt * 8 + 2 * tig;
            const float bx = __ldg(b1 + col);
            const float by = __ldg(b1 + col + 1);
            if (r0 < N_NODES) {
                float2 v;
                v.x = fmaxf(acc[mt][nt][0] + bx, 0.f);
                v.y = fmaxf(acc[mt][nt][1] + by, 0.f);
                *(float2*)(g_h + (size_t)r0 * D_HID + col) = v;
            }
            if (r0 + 8 < N_NODES) {
                float2 v;
                v.x = fmaxf(acc[mt][nt][2] + bx, 0.f);
                v.y = fmaxf(acc[mt][nt][3] + by, 0.f);
                *(float2*)(g_h + (size_t)(r0 + 8) * D_HID + col) = v;
            }
        }
    }
}

// ---------------------------------------------------------------------------
// GEMM2: X = h @ W2 + b2   (warp per row, W2 in smem)
// ---------------------------------------------------------------------------
__global__ __launch_bounds__(256) void gemm2_kernel(
    const float* __restrict__ W2,
    const float* __restrict__ b2)
{
    __shared__ float Ws[D_HID * D_OUT];  // 32 KB
    const int t = threadIdx.x;
    for (int i = t; i < D_HID * D_OUT; i += 256)
        Ws[i] = W2[i];
    __syncthreads();

    const int warp = t >> 5;
    const int lane = t & 31;
    const int row  = blockIdx.x * 8 + warp;
    if (row >= N_NODES) return;

    const float4* h4 = (const float4*)(g_h + (size_t)row * D_HID);
    float acc = __ldg(b2 + lane);
#pragma unroll
    for (int kk = 0; kk < D_HID / 4; kk++) {
        float4 hv = h4[kk];
        acc = fmaf(hv.x, Ws[(4 * kk + 0) * 32 + lane], acc);
        acc = fmaf(hv.y, Ws[(4 * kk + 1) * 32 + lane], acc);
        acc = fmaf(hv.z, Ws[(4 * kk + 2) * 32 + lane], acc);
        acc = fmaf(hv.w, Ws[(4 * kk + 3) * 32 + lane], acc);
    }
    g_x[(size_t)row * D_OUT + lane] = acc;
}

// ---------------------------------------------------------------------------
__global__ void zero_kernel(float4* out, int n4)
{
    int i = blockIdx.x * blockDim.x + threadIdx.x;
    if (i < n4) out[i] = make_float4(0.f, 0.f, 0.f, 0.f);
}

// ---------------------------------------------------------------------------
// Scatter: out[A_row[e], :] += A_data[e] * X[A_col[e], :]
// ---------------------------------------------------------------------------
__global__ __launch_bounds__(256) void scatter_kernel(
    const float* __restrict__ A_data,
    const int*   __restrict__ A_row,
    const int*   __restrict__ A_col,
    float*       __restrict__ out,
    int n_edges)
{
    int idx = blockIdx.x * blockDim.x + threadIdx.x;
    int e = idx >> 3;
    int q = idx & 7;
    if (e >= n_edges) return;

    float a = __ldg(A_data + e);
    int   r = __ldg(A_row + e);
    int   c = __ldg(A_col + e);

    float4 xv = *(const float4*)(g_x + (size_t)c * D_OUT + q * 4);
    float* o  = out + (size_t)r * D_OUT + q * 4;
    atomicAdd(o + 0, a * xv.x);
    atomicAdd(o + 1, a * xv.y);
    atomicAdd(o + 2, a * xv.z);
    atomicAdd(o + 3, a * xv.w);
}

// ---------------------------------------------------------------------------
extern "C" void kernel_launch(void* const* d_in, const int* in_sizes, int n_in,
                              void* d_out, int out_size)
{
    const float* F      = (const float*)d_in[0];
    const float* A_data = (const float*)d_in[1];
    const float* W1     = (const float*)d_in[2];
    const float* b1     = (const float*)d_in[3];
    const float* W2     = (const float*)d_in[4];
    const float* b2     = (const float*)d_in[5];
    const int*   A_row  = (const int*)d_in[6];
    const int*   A_col  = (const int*)d_in[7];
    float* out = (float*)d_out;

    const int n_edges = in_sizes[1];

    cudaFuncSetAttribute(gemm1_mma_kernel,
                         cudaFuncAttributeMaxDynamicSharedMemorySize, G1_SMEM);

    // W1 transpose + tf32 rounding (512 KB, trivial)
    prep_w1_kernel<<<dim3(D_IN / 32, D_HID / 32), dim3(32, 8)>>>(W1);

    // GEMM1 on tensor cores (mma.sync tf32)
    dim3 g1((N_NODES + 127) / 128, D_HID / 128);
    gemm1_mma_kernel<<<g1, 256, G1_SMEM>>>(F, b1);

    // GEMM2
    gemm2_kernel<<<(N_NODES + 7) / 8, 256>>>(W2, b2);

    // Zero output (poisoned by harness)
    int n4 = out_size / 4;
    zero_kernel<<<(n4 + 255) / 256, 256>>>((float4*)out, n4);

    // Scatter
    long long tot = (long long)n_edges * 8;
    int blocks = (int)((tot + 255) / 256);
    scatter_kernel<<<blocks, 256>>>(A_data, A_row, A_col, out, n_edges);
}

// round 4
// speedup vs baseline: 1.9860x; 1.3279x over previous
#include <cuda_runtime.h>
#include <cstdint>

#define N_NODES 100000
#define D_IN    512
#define D_HID   256
#define D_OUT   32

// Scratch (device globals: no runtime allocation allowed)
__device__ float g_x[(size_t)N_NODES * D_OUT];   // 12.8 MB
__device__ float g_w1t[D_HID * D_IN];            // W1^T, tf32-rounded

// ---------------------------------------------------------------------------
__device__ __forceinline__ float tf32_rna(float x) {
    uint32_t u;
    asm("cvt.rna.tf32.f32 %0, %1;" : "=r"(u) : "f"(x));
    return __uint_as_float(u);
}

__device__ __forceinline__ void mma_tf32(
    float& d0, float& d1, float& d2, float& d3,
    float a0, float a1, float a2, float a3,
    float b0, float b1)
{
    asm volatile(
        "mma.sync.aligned.m16n8k8.row.col.f32.tf32.tf32.f32 "
        "{%0,%1,%2,%3},{%4,%5,%6,%7},{%8,%9},{%0,%1,%2,%3};"
        : "+f"(d0), "+f"(d1), "+f"(d2), "+f"(d3)
        : "r"(__float_as_uint(a0)), "r"(__float_as_uint(a1)),
          "r"(__float_as_uint(a2)), "r"(__float_as_uint(a3)),
          "r"(__float_as_uint(b0)), "r"(__float_as_uint(b1)));
}

// ---------------------------------------------------------------------------
// Prep: W1[k][n] -> g_w1t[n][k], tf32-rounded. grid(16,8), block(32,8)
// ---------------------------------------------------------------------------
__global__ void prep_w1_kernel(const float* __restrict__ W1) {
    __shared__ float tile[32][33];
    const int tx = threadIdx.x;
    const int ty = threadIdx.y;
    const int kb = blockIdx.x * 32;
    const int nb = blockIdx.y * 32;
#pragma unroll
    for (int i = 0; i < 4; i++) {
        int k = ty + i * 8;
        tile[k][tx] = W1[(size_t)(kb + k) * D_HID + nb + tx];
    }
    __syncthreads();
#pragma unroll
    for (int i = 0; i < 4; i++) {
        int n = ty + i * 8;
        g_w1t[(size_t)(nb + n) * D_IN + kb + tx] = tf32_rna(tile[tx][n]);
    }
}

// ---------------------------------------------------------------------------
// Init: g_x[n][c] = b2[c]  (bias pre-load; gemm1 epilogue accumulates into it)
//       out = 0            (harness poisons d_out)
// ---------------------------------------------------------------------------
__global__ void init_kernel(float4* out, int n4_out, const float* __restrict__ b2)
{
    int i = blockIdx.x * blockDim.x + threadIdx.x;
    if (i < n4_out) {
        out[i] = make_float4(0.f, 0.f, 0.f, 0.f);
    } else {
        int j = i - n4_out;                       // float4 index into g_x
        if (j < N_NODES * (D_OUT / 4)) {
            int c = (j * 4) & (D_OUT - 1);
            float4 v;
            v.x = __ldg(b2 + c);     v.y = __ldg(b2 + c + 1);
            v.z = __ldg(b2 + c + 2); v.w = __ldg(b2 + c + 3);
            ((float4*)g_x)[j] = v;
        }
    }
}

// ---------------------------------------------------------------------------
// Fused GEMM1+GEMM2: X += relu(F @ W1 + b1)[:, n0:n0+128] @ W2[n0:n0+128, :]
// CTA 128x128x32 (mma.sync tf32), 8 warps (2M x 4N), warp tile 64x32.
// SMEM k-permuted layout: k-col c -> pos (c&3)*8 + (c>>2), row stride 36.
// Epilogue: relu(h) tile -> smem (reusing staging), small FFMA GEMM vs W2
// slice (smem), atomicAdd partial X into g_x.
// ---------------------------------------------------------------------------
#define G1_BK    32
#define G1_KIT   (D_IN / G1_BK)       // 16
#define G1_LD    36                   // padded floats per smem staging row
#define G1_BUF   (128 * G1_LD)        // floats per A (or B) tile
#define H_LD     132                  // padded stride for h tile (floats)
#define W2S_FLT  (128 * D_OUT)        // 4096 floats = 16 KB
#define G1_SMEM  ((2 * 2 * G1_BUF + W2S_FLT) * 4)   // 90112 bytes

__global__ __launch_bounds__(256) void gemm1_fused_kernel(
    const float* __restrict__ F,
    const float* __restrict__ b1,
    const float* __restrict__ W2)
{
    extern __shared__ float sm[];
    float* w2s = sm + 2 * 2 * G1_BUF;    // [128][32]

    const int t    = threadIdx.x;
    const int lane = t & 31;
    const int wid  = t >> 5;
    const int wm   = wid & 1;       // warp M index (0..1)
    const int wn   = wid >> 1;      // warp N index (0..3)
    const int g    = lane >> 2;     // group id (0..7)
    const int tig  = lane & 3;      // thread in group

    const int m0 = blockIdx.x * 128;
    const int n0 = blockIdx.y * 128;

    // Load W2 slice [n0:n0+128, 0:32] into smem (coalesced)
#pragma unroll
    for (int i = 0; i < W2S_FLT / 256; i++)
        w2s[t + i * 256] = W2[(size_t)n0 * D_OUT + t + i * 256];

    // Staging assignment: thread covers row (t>>1), k-half via (t&1)
    const int srow = t >> 1;            // 0..127
    const int kq   = (t & 1) * 16;      // k offset within BK tile
    const int spos = (t & 1) * 4;       // smem sub-position base

    int arow = m0 + srow;
    if (arow >= N_NODES) arow = N_NODES - 1;   // clamp; stores guarded later
    const float* Ag = F + (size_t)arow * D_IN + kq;
    const float* Bg = g_w1t + (size_t)(n0 + srow) * D_IN + kq;

    float4 ra[4], rb[4];
#pragma unroll
    for (int q = 0; q < 4; q++) {
        ra[q] = *(const float4*)(Ag + q * 4);
        rb[q] = *(const float4*)(Bg + q * 4);
    }
    {
        float* As = sm;
        float* Bs = sm + G1_BUF;
#pragma unroll
        for (int q = 0; q < 4; q++) {
            int p = srow * G1_LD + spos + q;
            As[p + 0 ] = tf32_rna(ra[q].x);
            As[p + 8 ] = tf32_rna(ra[q].y);
            As[p + 16] = tf32_rna(ra[q].z);
            As[p + 24] = tf32_rna(ra[q].w);
            Bs[p + 0 ] = rb[q].x;
            Bs[p + 8 ] = rb[q].y;
            Bs[p + 16] = rb[q].z;
            Bs[p + 24] = rb[q].w;
        }
    }
    __syncthreads();

    float acc[4][4][4];
#pragma unroll
    for (int i = 0; i < 4; i++)
#pragma unroll
        for (int j = 0; j < 4; j++)
#pragma unroll
            for (int c = 0; c < 4; c++) acc[i][j][c] = 0.f;

    const int am = wm * 64;
    const int bn = wn * 32;

    for (int kb = 0; kb < G1_KIT; kb++) {
        if (kb + 1 < G1_KIT) {
            const float* pa = Ag + (kb + 1) * G1_BK;
            const float* pb = Bg + (kb + 1) * G1_BK;
#pragma unroll
            for (int q = 0; q < 4; q++) {
                ra[q] = *(const float4*)(pa + q * 4);
                rb[q] = *(const float4*)(pb + q * 4);
            }
        }

        const float* As = sm + (kb & 1) * 2 * G1_BUF;
        const float* Bs = As + G1_BUF;

#pragma unroll
        for (int j = 0; j < 2; j++) {
            float4 afl[4], afh[4], bf[4];
#pragma unroll
            for (int mt = 0; mt < 4; mt++) {
                int r = am + mt * 16 + g;
                afl[mt] = *(const float4*)(As + r * G1_LD + tig * 8 + j * 4);
                afh[mt] = *(const float4*)(As + (r + 8) * G1_LD + tig * 8 + j * 4);
            }
#pragma unroll
            for (int nt = 0; nt < 4; nt++) {
                int n = bn + nt * 8 + g;
                bf[nt] = *(const float4*)(Bs + n * G1_LD + tig * 8 + j * 4);
            }
#pragma unroll
            for (int mt = 0; mt < 4; mt++) {
#pragma unroll
                for (int nt = 0; nt < 4; nt++) {
                    mma_tf32(acc[mt][nt][0], acc[mt][nt][1],
                             acc[mt][nt][2], acc[mt][nt][3],
                             afl[mt].x, afh[mt].x, afl[mt].y, afh[mt].y,
                             bf[nt].x,  bf[nt].y);
                    mma_tf32(acc[mt][nt][0], acc[mt][nt][1],
                             acc[mt][nt][2], acc[mt][nt][3],
                             afl[mt].z, afh[mt].z, afl[mt].w, afh[mt].w,
                             bf[nt].z,  bf[nt].w);
                }
            }
        }

        if (kb + 1 < G1_KIT) {
            float* Aw = sm + ((kb + 1) & 1) * 2 * G1_BUF;
            float* Bw = Aw + G1_BUF;
#pragma unroll
            for (int q = 0; q < 4; q++) {
                int p = srow * G1_LD + spos + q;
                Aw[p + 0 ] = tf32_rna(ra[q].x);
                Aw[p + 8 ] = tf32_rna(ra[q].y);
                Aw[p + 16] = tf32_rna(ra[q].z);
                Aw[p + 24] = tf32_rna(ra[q].w);
                Bw[p + 0 ] = rb[q].x;
                Bw[p + 8 ] = rb[q].y;
                Bw[p + 16] = rb[q].z;
                Bw[p + 24] = rb[q].w;
            }
            __syncthreads();
        }
    }

    // ---- epilogue 1: bias + relu, spill h tile to smem (reuse staging) ----
    __syncthreads();   // all mma fragment reads done before overwrite
    float* hs = sm;    // [128][H_LD]
#pragma unroll
    for (int mt = 0; mt < 4; mt++) {
        const int lr = am + mt * 16 + g;           // local row
#pragma unroll
        for (int nt = 0; nt < 4; nt++) {
            const int lc = bn + nt * 8 + 2 * tig;  // local col
            const float bx = __ldg(b1 + n0 + lc);
            const float by = __ldg(b1 + n0 + lc + 1);
            float2 v0, v1;
            v0.x = fmaxf(acc[mt][nt][0] + bx, 0.f);
            v0.y = fmaxf(acc[mt][nt][1] + by, 0.f);
            v1.x = fmaxf(acc[mt][nt][2] + bx, 0.f);
            v1.y = fmaxf(acc[mt][nt][3] + by, 0.f);
            *(float2*)(hs + lr * H_LD + lc)       = v0;
            *(float2*)(hs + (lr + 8) * H_LD + lc) = v1;
        }
    }
    __syncthreads();

    // ---- epilogue 2: X partial = h_tile(128x128) @ w2s(128x32) ----
    // warp w handles rows [16w, 16w+16), lane = output col.
    float xacc[16];
#pragma unroll
    for (int r = 0; r < 16; r++) xacc[r] = 0.f;

    const int rbase = wid * 16;
#pragma unroll 4
    for (int k4 = 0; k4 < 32; k4++) {
        const float w0 = w2s[(4 * k4 + 0) * D_OUT + lane];
        const float w1 = w2s[(4 * k4 + 1) * D_OUT + lane];
        const float w2v = w2s[(4 * k4 + 2) * D_OUT + lane];
        const float w3 = w2s[(4 * k4 + 3) * D_OUT + lane];
#pragma unroll
        for (int r = 0; r < 16; r++) {
            float4 hv = *(const float4*)(hs + (rbase + r) * H_LD + 4 * k4);
            xacc[r] = fmaf(hv.x, w0, xacc[r]);
            xacc[r] = fmaf(hv.y, w1, xacc[r]);
            xacc[r] = fmaf(hv.z, w2v, xacc[r]);
            xacc[r] = fmaf(hv.w, w3, xacc[r]);
        }
    }

#pragma unroll
    for (int r = 0; r < 16; r++) {
        const int grow = m0 + rbase + r;
        if (grow < N_NODES)
            atomicAdd(g_x + (size_t)grow * D_OUT + lane, xacc[r]);
    }
}

// ---------------------------------------------------------------------------
// Scatter: out[A_row[e], :] += A_data[e] * X[A_col[e], :]
// ---------------------------------------------------------------------------
__global__ __launch_bounds__(256) void scatter_kernel(
    const float* __restrict__ A_data,
    const int*   __restrict__ A_row,
    const int*   __restrict__ A_col,
    float*       __restrict__ out,
    int n_edges)
{
    int idx = blockIdx.x * blockDim.x + threadIdx.x;
    int e = idx >> 3;
    int q = idx & 7;
    if (e >= n_edges) return;

    float a = __ldg(A_data + e);
    int   r = __ldg(A_row + e);
    int   c = __ldg(A_col + e);

    float4 xv = *(const float4*)(g_x + (size_t)c * D_OUT + q * 4);
    float* o  = out + (size_t)r * D_OUT + q * 4;
    atomicAdd(o + 0, a * xv.x);
    atomicAdd(o + 1, a * xv.y);
    atomicAdd(o + 2, a * xv.z);
    atomicAdd(o + 3, a * xv.w);
}

// ---------------------------------------------------------------------------
extern "C" void kernel_launch(void* const* d_in, const int* in_sizes, int n_in,
                              void* d_out, int out_size)
{
    const float* F      = (const float*)d_in[0];
    const float* A_data = (const float*)d_in[1];
    const float* W1     = (const float*)d_in[2];
    const float* b1     = (const float*)d_in[3];
    const float* W2     = (const float*)d_in[4];
    const float* b2     = (const float*)d_in[5];
    const int*   A_row  = (const int*)d_in[6];
    const int*   A_col  = (const int*)d_in[7];
    float* out = (float*)d_out;

    const int n_edges = in_sizes[1];

    cudaFuncSetAttribute(gemm1_fused_kernel,
                         cudaFuncAttributeMaxDynamicSharedMemorySize, G1_SMEM);

    // W1 transpose + tf32 rounding
    prep_w1_kernel<<<dim3(D_IN / 32, D_HID / 32), dim3(32, 8)>>>(W1);

    // out = 0, g_x = b2 (broadcast)
    const int n4_out = out_size / 4;
    const int n4_x   = N_NODES * D_OUT / 4;
    init_kernel<<<(n4_out + n4_x + 255) / 256, 256>>>((float4*)out, n4_out, b2);

    // Fused GEMM1+GEMM2 (tensor cores + FFMA epilogue)
    dim3 g1((N_NODES + 127) / 128, D_HID / 128);
    gemm1_fused_kernel<<<g1, 256, G1_SMEM>>>(F, b1, W2);

    // Scatter
    long long tot = (long long)n_edges * 8;
    int blocks = (int)((tot + 255) / 256);
    scatter_kernel<<<blocks, 256>>>(A_data, A_row, A_col, out, n_edges);
}

// round 5
// speedup vs baseline: 2.7518x; 1.3856x over previous
#include <cuda_runtime.h>
#include <cstdint>

#define N_NODES 100000
#define D_IN    512
#define D_HID   256
#define D_OUT   32

// Scratch (device globals: no runtime allocation allowed)
__device__ float g_x[(size_t)N_NODES * D_OUT];   // 12.8 MB
__device__ float g_w1t[D_HID * D_IN];            // W1^T, tf32-rounded

// ---------------------------------------------------------------------------
__device__ __forceinline__ float tf32_rna(float x) {
    uint32_t u;
    asm("cvt.rna.tf32.f32 %0, %1;" : "=r"(u) : "f"(x));
    return __uint_as_float(u);
}

__device__ __forceinline__ void mma_tf32(
    float& d0, float& d1, float& d2, float& d3,
    float a0, float a1, float a2, float a3,
    float b0, float b1)
{
    asm volatile(
        "mma.sync.aligned.m16n8k8.row.col.f32.tf32.tf32.f32 "
        "{%0,%1,%2,%3},{%4,%5,%6,%7},{%8,%9},{%0,%1,%2,%3};"
        : "+f"(d0), "+f"(d1), "+f"(d2), "+f"(d3)
        : "r"(__float_as_uint(a0)), "r"(__float_as_uint(a1)),
          "r"(__float_as_uint(a2)), "r"(__float_as_uint(a3)),
          "r"(__float_as_uint(b0)), "r"(__float_as_uint(b1)));
}

__device__ __forceinline__ void red_v2(float* p, float v0, float v1) {
    asm volatile("red.global.add.v2.f32 [%0], {%1, %2};"
                 :: "l"(p), "f"(v0), "f"(v1) : "memory");
}

// ---------------------------------------------------------------------------
// Prep: W1[k][n] -> g_w1t[n][k], tf32-rounded. grid(16,8), block(32,8)
// ---------------------------------------------------------------------------
__global__ void prep_w1_kernel(const float* __restrict__ W1) {
    __shared__ float tile[32][33];
    const int tx = threadIdx.x;
    const int ty = threadIdx.y;
    const int kb = blockIdx.x * 32;
    const int nb = blockIdx.y * 32;
#pragma unroll
    for (int i = 0; i < 4; i++) {
        int k = ty + i * 8;
        tile[k][tx] = W1[(size_t)(kb + k) * D_HID + nb + tx];
    }
    __syncthreads();
#pragma unroll
    for (int i = 0; i < 4; i++) {
        int n = ty + i * 8;
        g_w1t[(size_t)(nb + n) * D_IN + kb + tx] = tf32_rna(tile[tx][n]);
    }
}

// ---------------------------------------------------------------------------
// Init: g_x[n][c] = b2[c] (epilogue accumulates into it); out = 0
// ---------------------------------------------------------------------------
__global__ void init_kernel(float4* out, int n4_out, const float* __restrict__ b2)
{
    int i = blockIdx.x * blockDim.x + threadIdx.x;
    if (i < n4_out) {
        out[i] = make_float4(0.f, 0.f, 0.f, 0.f);
    } else {
        int j = i - n4_out;
        if (j < N_NODES * (D_OUT / 4)) {
            int c = (j * 4) & (D_OUT - 1);
            float4 v;
            v.x = __ldg(b2 + c);     v.y = __ldg(b2 + c + 1);
            v.z = __ldg(b2 + c + 2); v.w = __ldg(b2 + c + 3);
            ((float4*)g_x)[j] = v;
        }
    }
}

// ---------------------------------------------------------------------------
// Fused GEMM: X += relu(F @ W1 + b1)[:, n0:n0+128] @ W2[n0:n0+128, :]
// CTA 128x128x32, 512 threads, 16 warps (4M x 4N), warp tile 32x32.
// SMEM k-permuted layout: k-col c -> pos (c&3)*8 + (c>>2), row stride 36.
// Epilogue on tensor cores: relu(h) -> 4 staging buffers (k-permuted),
// W2 slice pre-permuted, h @ W2 via mma, red into g_x.
// ---------------------------------------------------------------------------
#define G1_BK   32
#define G1_KIT  (D_IN / G1_BK)       // 16
#define G1_LD   36
#define G1_BUF  (128 * G1_LD)        // 4608 floats
#define W2P_KB  (32 * G1_LD)         // 1152 floats per k-block
#define G1_SMEM ((4 * G1_BUF + 4 * W2P_KB) * 4)   // 92160 bytes

__global__ __launch_bounds__(512) void gemm_fused_kernel(
    const float* __restrict__ F,
    const float* __restrict__ b1,
    const float* __restrict__ W2)
{
    extern __shared__ float sm[];
    float* w2p = sm + 4 * G1_BUF;

    const int t    = threadIdx.x;
    const int lane = t & 31;
    const int wid  = t >> 5;           // 0..15
    const int wm   = wid & 3;          // warp M (0..3)
    const int wn   = wid >> 2;         // warp N (0..3)
    const int g    = lane >> 2;        // 0..7
    const int tig  = lane & 3;         // 0..3

    const int n0 = blockIdx.x * 128;   // N fastest -> F L2 reuse
    const int m0 = blockIdx.y * 128;

    // ---- pre-permute W2 slice [n0:n0+128, 0:32] into w2p (tf32-rounded) ----
#pragma unroll
    for (int i = 0; i < 8; i++) {
        int idx = t + i * 512;                  // 0..4095
        int c   = idx >> 5;                     // h-col 0..127
        int np  = idx & 31;                     // out col
        float v = tf32_rna(W2[(size_t)(n0 + c) * D_OUT + np]);
        int cc  = c & 31;
        int pos = (cc & 3) * 8 + (cc >> 2);
        w2p[(c >> 5) * W2P_KB + np * G1_LD + pos] = v;
    }

    // ---- staging assignment: row = t>>2, k-cols [(t&3)*8, +8) ----
    const int srow = t >> 2;
    const int kq   = (t & 3) * 8;

    int arow = m0 + srow;
    if (arow >= N_NODES) arow = N_NODES - 1;   // clamp; stores guarded
    const float* Ag = F + (size_t)arow * D_IN + kq;
    const float* Bg = g_w1t + (size_t)(n0 + srow) * D_IN + kq;

    float4 ra[2], rb[2];
#pragma unroll
    for (int q = 0; q < 2; q++) {
        ra[q] = *(const float4*)(Ag + q * 4);
        rb[q] = *(const float4*)(Bg + q * 4);
    }
    {
        float* As = sm;
        float* Bs = sm + G1_BUF;
        const int pb = srow * G1_LD + 2 * (t & 3);
#pragma unroll
        for (int q = 0; q < 2; q++) {
            // element e of float4 q -> pos e*8 + 2*(t&3) + q  (A raw; HW truncates)
            As[pb + q + 0 ] = ra[q].x;
            As[pb + q + 8 ] = ra[q].y;
            As[pb + q + 16] = ra[q].z;
            As[pb + q + 24] = ra[q].w;
            Bs[pb + q + 0 ] = rb[q].x;
            Bs[pb + q + 8 ] = rb[q].y;
            Bs[pb + q + 16] = rb[q].z;
            Bs[pb + q + 24] = rb[q].w;
        }
    }
    __syncthreads();

    float acc[2][4][4];
#pragma unroll
    for (int i = 0; i < 2; i++)
#pragma unroll
        for (int j = 0; j < 4; j++)
#pragma unroll
            for (int c = 0; c < 4; c++) acc[i][j][c] = 0.f;

    const int am = wm * 32;
    const int bn = wn * 32;

    for (int kb = 0; kb < G1_KIT; kb++) {
        if (kb + 1 < G1_KIT) {
            const float* pa = Ag + (kb + 1) * G1_BK;
            const float* pb2 = Bg + (kb + 1) * G1_BK;
#pragma unroll
            for (int q = 0; q < 2; q++) {
                ra[q] = *(const float4*)(pa + q * 4);
                rb[q] = *(const float4*)(pb2 + q * 4);
            }
        }

        const float* As = sm + (kb & 1) * 2 * G1_BUF;
        const float* Bs = As + G1_BUF;

#pragma unroll
        for (int j = 0; j < 2; j++) {
            float4 afl[2], afh[2], bf[4];
#pragma unroll
            for (int mt = 0; mt < 2; mt++) {
                int r = am + mt * 16 + g;
                afl[mt] = *(const float4*)(As + r * G1_LD + tig * 8 + j * 4);
                afh[mt] = *(const float4*)(As + (r + 8) * G1_LD + tig * 8 + j * 4);
            }
#pragma unroll
            for (int nt = 0; nt < 4; nt++) {
                int n = bn + nt * 8 + g;
                bf[nt] = *(const float4*)(Bs + n * G1_LD + tig * 8 + j * 4);
            }
#pragma unroll
            for (int mt = 0; mt < 2; mt++) {
#pragma unroll
                for (int nt = 0; nt < 4; nt++) {
                    mma_tf32(acc[mt][nt][0], acc[mt][nt][1],
                             acc[mt][nt][2], acc[mt][nt][3],
                             afl[mt].x, afh[mt].x, afl[mt].y, afh[mt].y,
                             bf[nt].x,  bf[nt].y);
                    mma_tf32(acc[mt][nt][0], acc[mt][nt][1],
                             acc[mt][nt][2], acc[mt][nt][3],
                             afl[mt].z, afh[mt].z, afl[mt].w, afh[mt].w,
                             bf[nt].z,  bf[nt].w);
                }
            }
        }

        if (kb + 1 < G1_KIT) {
            float* Aw = sm + ((kb + 1) & 1) * 2 * G1_BUF;
            float* Bw = Aw + G1_BUF;
            const int pb = srow * G1_LD + 2 * (t & 3);
#pragma unroll
            for (int q = 0; q < 2; q++) {
                Aw[pb + q + 0 ] = ra[q].x;
                Aw[pb + q + 8 ] = ra[q].y;
                Aw[pb + q + 16] = ra[q].z;
                Aw[pb + q + 24] = ra[q].w;
                Bw[pb + q + 0 ] = rb[q].x;
                Bw[pb + q + 8 ] = rb[q].y;
                Bw[pb + q + 16] = rb[q].z;
                Bw[pb + q + 24] = rb[q].w;
            }
            __syncthreads();
        }
    }

    // ---- epilogue 1: bias + relu -> staging buffers, k-permuted, tf32 ----
    __syncthreads();
    // h-col lc lives in buffer (lc>>5) at row stride 36, pos((lc&31))
    // lc = bn + nt*8 + 2*tig (+1); buffer index = wn.
    {
        float* hb = sm + wn * G1_BUF;
#pragma unroll
        for (int mt = 0; mt < 2; mt++) {
            const int lr = am + mt * 16 + g;
#pragma unroll
            for (int nt = 0; nt < 4; nt++) {
                const int cc  = nt * 8 + 2 * tig;          // 0..31 (even)
                const int pos = (cc & 3) * 8 + (cc >> 2);
                const float bx = __ldg(b1 + n0 + bn + cc);
                const float by = __ldg(b1 + n0 + bn + cc + 1);
                hb[lr * G1_LD + pos]           = tf32_rna(fmaxf(acc[mt][nt][0] + bx, 0.f));
                hb[lr * G1_LD + pos + 8]       = tf32_rna(fmaxf(acc[mt][nt][1] + by, 0.f));
                hb[(lr + 8) * G1_LD + pos]     = tf32_rna(fmaxf(acc[mt][nt][2] + bx, 0.f));
                hb[(lr + 8) * G1_LD + pos + 8] = tf32_rna(fmaxf(acc[mt][nt][3] + by, 0.f));
            }
        }
    }
    __syncthreads();

    // ---- epilogue 2: X partial = h(128x128) @ W2slice(128x32) via mma ----
    // 16 warps: wm2 = wid&7 -> m rows [16*wm2,+16); wn2 = wid>>3 -> n' [16*wn2,+16)
    {
        const int wm2 = wid & 7;
        const int wn2 = wid >> 3;
        float xc[2][4];
#pragma unroll
        for (int nt = 0; nt < 2; nt++)
#pragma unroll
            for (int c = 0; c < 4; c++) xc[nt][c] = 0.f;

#pragma unroll
        for (int kb2 = 0; kb2 < 4; kb2++) {
            const float* Ah = sm + kb2 * G1_BUF;
            const float* Wp = w2p + kb2 * W2P_KB;
#pragma unroll
            for (int j = 0; j < 2; j++) {
                float4 al = *(const float4*)(Ah + (wm2 * 16 + g) * G1_LD + tig * 8 + j * 4);
                float4 ah = *(const float4*)(Ah + (wm2 * 16 + g + 8) * G1_LD + tig * 8 + j * 4);
                float4 bw0 = *(const float4*)(Wp + (wn2 * 16 + g) * G1_LD + tig * 8 + j * 4);
                float4 bw1 = *(const float4*)(Wp + (wn2 * 16 + 8 + g) * G1_LD + tig * 8 + j * 4);
                mma_tf32(xc[0][0], xc[0][1], xc[0][2], xc[0][3],
                         al.x, ah.x, al.y, ah.y, bw0.x, bw0.y);
                mma_tf32(xc[0][0], xc[0][1], xc[0][2], xc[0][3],
                         al.z, ah.z, al.w, ah.w, bw0.z, bw0.w);
                mma_tf32(xc[1][0], xc[1][1], xc[1][2], xc[1][3],
                         al.x, ah.x, al.y, ah.y, bw1.x, bw1.y);
                mma_tf32(xc[1][0], xc[1][1], xc[1][2], xc[1][3],
                         al.z, ah.z, al.w, ah.w, bw1.z, bw1.w);
            }
        }

        const int mrow = m0 + wm2 * 16 + g;
#pragma unroll
        for (int nt = 0; nt < 2; nt++) {
            const int np = wn2 * 16 + nt * 8 + 2 * tig;
            if (mrow < N_NODES)
                red_v2(g_x + (size_t)mrow * D_OUT + np, xc[nt][0], xc[nt][1]);
            if (mrow + 8 < N_NODES)
                red_v2(g_x + (size_t)(mrow + 8) * D_OUT + np, xc[nt][2], xc[nt][3]);
        }
    }
}

// ---------------------------------------------------------------------------
// Scatter: out[A_row[e], :] += A_data[e] * X[A_col[e], :]  (v2 reductions)
// ---------------------------------------------------------------------------
__global__ __launch_bounds__(256) void scatter_kernel(
    const float* __restrict__ A_data,
    const int*   __restrict__ A_row,
    const int*   __restrict__ A_col,
    float*       __restrict__ out,
    int n_edges)
{
    int idx = blockIdx.x * blockDim.x + threadIdx.x;
    int e = idx >> 3;
    int q = idx & 7;
    if (e >= n_edges) return;

    float a = __ldg(A_data + e);
    int   r = __ldg(A_row + e);
    int   c = __ldg(A_col + e);

    float4 xv = *(const float4*)(g_x + (size_t)c * D_OUT + q * 4);
    float* o  = out + (size_t)r * D_OUT + q * 4;
    red_v2(o + 0, a * xv.x, a * xv.y);
    red_v2(o + 2, a * xv.z, a * xv.w);
}

// ---------------------------------------------------------------------------
extern "C" void kernel_launch(void* const* d_in, const int* in_sizes, int n_in,
                              void* d_out, int out_size)
{
    const float* F      = (const float*)d_in[0];
    const float* A_data = (const float*)d_in[1];
    const float* W1     = (const float*)d_in[2];
    const float* b1     = (const float*)d_in[3];
    const float* W2     = (const float*)d_in[4];
    const float* b2     = (const float*)d_in[5];
    const int*   A_row  = (const int*)d_in[6];
    const int*   A_col  = (const int*)d_in[7];
    float* out = (float*)d_out;

    const int n_edges = in_sizes[1];

    cudaFuncSetAttribute(gemm_fused_kernel,
                         cudaFuncAttributeMaxDynamicSharedMemorySize, G1_SMEM);

    // W1 transpose + tf32 rounding
    prep_w1_kernel<<<dim3(D_IN / 32, D_HID / 32), dim3(32, 8)>>>(W1);

    // out = 0, g_x = b2
    const int n4_out = out_size / 4;
    const int n4_x   = N_NODES * D_OUT / 4;
    init_kernel<<<(n4_out + n4_x + 255) / 256, 256>>>((float4*)out, n4_out, b2);

    // Fused GEMM (N fastest in grid.x for F L2 reuse)
    dim3 g1(D_HID / 128, (N_NODES + 127) / 128);
    gemm_fused_kernel<<<g1, 512, G1_SMEM>>>(F, b1, W2);

    // Scatter
    long long tot = (long long)n_edges * 8;
    int blocks = (int)((tot + 255) / 256);
    scatter_kernel<<<blocks, 256>>>(A_data, A_row, A_col, out, n_edges);
}